// round 1
// baseline (speedup 1.0000x reference)
#include <cuda_runtime.h>

#define TDIM 1024
#define JDIM 128
#define BDIM 32
#define DDIM 256
#define TT   64
#define VNEG -1e30f

// scratch (static device arrays — no allocation)
__device__ float g_mbuf[BDIM * TDIM];
__device__ float g_q2c[BDIM * DDIM];

// shared memory layout (in floats)
#define OFF_QS    0                      // 128*256 swizzled question
#define OFF_CWS   (128*256)              // union: cws 64*260  /  pT 128*68
#define OFF_SWC   (OFF_CWS + 64*260)
#define OFF_SWQ   (OFF_SWC + 256)
#define OFF_SWCQ  (OFF_SWQ + 256)
#define OFF_QPROJ (OFF_SWCQ + 256)
#define OFF_CPROJ (OFF_QPROJ + 128)
#define SMEM_FLOATS (OFF_CPROJ + 64)

__global__ __launch_bounds__(256, 1)
void bidaf_k1(const float* __restrict__ ctx, const float* __restrict__ qst,
              const int* __restrict__ con_lens, const int* __restrict__ qu_lens,
              const float* __restrict__ att_w, float* __restrict__ G)
{
    extern __shared__ float sm[];
    float* qs    = sm + OFF_QS;
    float* cws   = sm + OFF_CWS;
    float* pT    = cws;                 // reuse after cross-matmul
    float* swc   = sm + OFF_SWC;
    float* swq   = sm + OFF_SWQ;
    float* swcq  = sm + OFF_SWCQ;
    float* qproj = sm + OFF_QPROJ;
    float* cproj = sm + OFF_CPROJ;

    const int tid  = threadIdx.x;
    const int b    = blockIdx.y;
    const int t0   = blockIdx.x * TT;
    const int clen = con_lens[b];
    const int qlen = qu_lens[b];

    // weights into smem
    swc[tid]  = att_w[tid];
    swq[tid]  = att_w[DDIM + tid];
    swcq[tid] = att_w[2 * DDIM + tid];
    __syncthreads();

    const int sub   = tid & 3;
    const int rowid = tid >> 2;

    // ---- load question tile (swizzled) + qproj -------------------------
    #pragma unroll
    for (int pass = 0; pass < 2; ++pass) {
        const int j = pass * 64 + rowid;
        const float* src = qst + ((size_t)j * BDIM + b) * DDIM;
        const int xr = j & 28;
        float qp = 0.f;
        #pragma unroll
        for (int i = 0; i < 16; ++i) {
            const int d = i * 16 + sub * 4;
            float4 v = *(const float4*)(src + d);
            *(float4*)&qs[j * DDIM + (d ^ xr)] = v;
            qp += v.x * swq[d] + v.y * swq[d + 1] + v.z * swq[d + 2] + v.w * swq[d + 3];
        }
        qp += __shfl_xor_sync(0xffffffffu, qp, 1);
        qp += __shfl_xor_sync(0xffffffffu, qp, 2);
        if (sub == 0) qproj[j] = qp;
    }

    // ---- load context tile -> cw = ctx*w_cq, cproj --------------------
    {
        const int tl = rowid;
        const int t  = t0 + tl;
        const float* src = ctx + ((size_t)t * BDIM + b) * DDIM;
        float cp = 0.f;
        #pragma unroll
        for (int i = 0; i < 16; ++i) {
            const int d = i * 16 + sub * 4;
            float4 v = *(const float4*)(src + d);
            float4 w = *(const float4*)&swcq[d];
            float4 cv;
            cv.x = v.x * w.x; cv.y = v.y * w.y; cv.z = v.z * w.z; cv.w = v.w * w.w;
            *(float4*)&cws[tl * 260 + d] = cv;
            float4 wc = *(const float4*)&swc[d];
            cp += v.x * wc.x + v.y * wc.y + v.z * wc.z + v.w * wc.w;
        }
        cp += __shfl_xor_sync(0xffffffffu, cp, 1);
        cp += __shfl_xor_sync(0xffffffffu, cp, 2);
        if (sub == 0) cproj[tl] = cp;
    }
    __syncthreads();

    const int tx  = tid & 15;
    const int ty  = tid >> 4;
    const int j0  = tx * 4;
    const int xr0 = j0 & 28;

    // ---- cross matmul: S[4t][8j] ---------------------------------------
    float acc[4][8];
    #pragma unroll
    for (int i = 0; i < 4; ++i)
        #pragma unroll
        for (int jj = 0; jj < 8; ++jj) acc[i][jj] = 0.f;

    #pragma unroll 2
    for (int d = 0; d < DDIM; d += 4) {
        float4 qv[8];
        #pragma unroll
        for (int jj = 0; jj < 4; ++jj) {
            qv[jj]     = *(const float4*)&qs[(j0 + jj) * DDIM + (d ^ xr0)];
            qv[4 + jj] = *(const float4*)&qs[(j0 + 64 + jj) * DDIM + (d ^ xr0)];
        }
        float4 cv[4];
        #pragma unroll
        for (int i = 0; i < 4; ++i)
            cv[i] = *(const float4*)&cws[(ty * 4 + i) * 260 + d];
        #pragma unroll
        for (int i = 0; i < 4; ++i)
            #pragma unroll
            for (int jj = 0; jj < 8; ++jj)
                acc[i][jj] += cv[i].x * qv[jj].x + cv[i].y * qv[jj].y
                            + cv[i].z * qv[jj].z + cv[i].w * qv[jj].w;
    }

    // ---- masked softmax over j (16-lane shfl reduce) --------------------
    float pr[4][8];
    #pragma unroll
    for (int i = 0; i < 4; ++i) {
        const int t = t0 + ty * 4 + i;
        const bool tval = t < clen;
        const float cpv = cproj[ty * 4 + i];
        float s[8];
        #pragma unroll
        for (int jj = 0; jj < 8; ++jj) {
            const int j = (jj < 4) ? (j0 + jj) : (j0 + 60 + jj);
            const float sv = cpv + qproj[j] + acc[i][jj];
            s[jj] = (tval && (j < qlen)) ? sv : VNEG;
        }
        float mx = s[0];
        #pragma unroll
        for (int jj = 1; jj < 8; ++jj) mx = fmaxf(mx, s[jj]);
        #pragma unroll
        for (int o = 1; o < 16; o <<= 1) mx = fmaxf(mx, __shfl_xor_sync(0xffffffffu, mx, o));
        float sum = 0.f;
        #pragma unroll
        for (int jj = 0; jj < 8; ++jj) { s[jj] = __expf(s[jj] - mx); sum += s[jj]; }
        #pragma unroll
        for (int o = 1; o < 16; o <<= 1) sum += __shfl_xor_sync(0xffffffffu, sum, o);
        const float inv = 1.f / sum;
        #pragma unroll
        for (int jj = 0; jj < 8; ++jj) pr[i][jj] = s[jj] * inv;
        if (tx == 0) g_mbuf[b * TDIM + t] = mx;
    }
    __syncthreads();   // all cws reads complete before pT overwrite

    // ---- stage P transposed: pT[j][t] ----------------------------------
    #pragma unroll
    for (int jj = 0; jj < 8; ++jj) {
        const int j = (jj < 4) ? (j0 + jj) : (j0 + 60 + jj);
        #pragma unroll
        for (int i = 0; i < 4; ++i)
            pT[j * 68 + ty * 4 + i] = pr[i][jj];
    }
    __syncthreads();

    // ---- second matmul: c2q[4t][16d] = P @ Q ---------------------------
    float c2[4][16];
    #pragma unroll
    for (int i = 0; i < 4; ++i)
        #pragma unroll
        for (int k = 0; k < 16; ++k) c2[i][k] = 0.f;

    const int d0 = tx * 4;
    #pragma unroll 2
    for (int j = 0; j < JDIM; ++j) {
        float4 pv = *(const float4*)&pT[j * 68 + ty * 4];
        const int xr = j & 28;
        float4 qv2[4];
        #pragma unroll
        for (int k = 0; k < 4; ++k)
            qv2[k] = *(const float4*)&qs[j * DDIM + ((d0 + 64 * k) ^ xr)];
        float pa[4] = {pv.x, pv.y, pv.z, pv.w};
        #pragma unroll
        for (int i = 0; i < 4; ++i)
            #pragma unroll
            for (int k = 0; k < 4; ++k) {
                c2[i][k * 4 + 0] += pa[i] * qv2[k].x;
                c2[i][k * 4 + 1] += pa[i] * qv2[k].y;
                c2[i][k * 4 + 2] += pa[i] * qv2[k].z;
                c2[i][k * 4 + 3] += pa[i] * qv2[k].w;
            }
    }

    // ---- epilogue: G[:, 0:768] ------------------------------------------
    #pragma unroll
    for (int i = 0; i < 4; ++i) {
        const int t = t0 + ty * 4 + i;
        const float tv = (t < clen) ? 1.f : 0.f;
        const float* crow = ctx + ((size_t)t * BDIM + b) * DDIM;
        float* grow = G + ((size_t)b * TDIM + t) * (4 * DDIM);
        #pragma unroll
        for (int k = 0; k < 4; ++k) {
            const int d = d0 + 64 * k;
            float4 cvv = *(const float4*)(crow + d);
            float4 aq;
            aq.x = c2[i][k * 4 + 0]; aq.y = c2[i][k * 4 + 1];
            aq.z = c2[i][k * 4 + 2]; aq.w = c2[i][k * 4 + 3];
            float4 o0, o1, o2;
            o0.x = cvv.x * tv;        o0.y = cvv.y * tv;        o0.z = cvv.z * tv;        o0.w = cvv.w * tv;
            o1.x = aq.x * tv;         o1.y = aq.y * tv;         o1.z = aq.z * tv;         o1.w = aq.w * tv;
            o2.x = cvv.x * aq.x * tv; o2.y = cvv.y * aq.y * tv; o2.z = cvv.z * aq.z * tv; o2.w = cvv.w * aq.w * tv;
            *(float4*)(grow + d)        = o0;
            *(float4*)(grow + 256 + d)  = o1;
            *(float4*)(grow + 512 + d)  = o2;
        }
    }
}

// ---- kernel 2: value = softmax_t(m); q2c_vec = value . context ----------
__global__ __launch_bounds__(256, 1)
void bidaf_k2(const float* __restrict__ ctx)
{
    __shared__ float vbuf[TDIM];
    __shared__ float red[8];
    __shared__ float4 pb[4][64];
    const int b = blockIdx.x;
    const int tid = threadIdx.x;
    const int lane = tid & 31, wid = tid >> 5;

    float mv[4];
    float mx = -3.4e38f;
    #pragma unroll
    for (int r = 0; r < 4; ++r) {
        mv[r] = g_mbuf[b * TDIM + r * 256 + tid];
        mx = fmaxf(mx, mv[r]);
    }
    #pragma unroll
    for (int o = 16; o > 0; o >>= 1) mx = fmaxf(mx, __shfl_xor_sync(0xffffffffu, mx, o));
    if (lane == 0) red[wid] = mx;
    __syncthreads();
    mx = red[0];
    #pragma unroll
    for (int w = 1; w < 8; ++w) mx = fmaxf(mx, red[w]);

    float sum = 0.f;
    #pragma unroll
    for (int r = 0; r < 4; ++r) {
        float e = __expf(mv[r] - mx);
        vbuf[r * 256 + tid] = e;
        sum += e;
    }
    #pragma unroll
    for (int o = 16; o > 0; o >>= 1) sum += __shfl_xor_sync(0xffffffffu, sum, o);
    __syncthreads();
    if (lane == 0) red[wid] = sum;
    __syncthreads();
    float tot = 0.f;
    #pragma unroll
    for (int w = 0; w < 8; ++w) tot += red[w];
    const float inv = 1.f / tot;

    const int dq = (tid & 63) * 4;
    const int chunk = tid >> 6;
    float4 acc = {0.f, 0.f, 0.f, 0.f};
    for (int tt = chunk * 256; tt < chunk * 256 + 256; ++tt) {
        const float v = vbuf[tt];
        float4 c = *(const float4*)&ctx[((size_t)tt * BDIM + b) * DDIM + dq];
        acc.x += v * c.x; acc.y += v * c.y; acc.z += v * c.z; acc.w += v * c.w;
    }
    pb[chunk][tid & 63] = acc;
    __syncthreads();
    if (chunk == 0) {
        float4 s0 = pb[0][tid], s1 = pb[1][tid], s2 = pb[2][tid], s3 = pb[3][tid];
        float4 s;
        s.x = (s0.x + s1.x + s2.x + s3.x) * inv;
        s.y = (s0.y + s1.y + s2.y + s3.y) * inv;
        s.z = (s0.z + s1.z + s2.z + s3.z) * inv;
        s.w = (s0.w + s1.w + s2.w + s3.w) * inv;
        *(float4*)&g_q2c[b * DDIM + dq] = s;
    }
}

// ---- kernel 3: G[:, 768:1024] = ctx * q2c * t_valid ----------------------
__global__ void bidaf_k3(const float* __restrict__ ctx, const int* __restrict__ con_lens,
                         float* __restrict__ G)
{
    const int gid = blockIdx.x * 256 + threadIdx.x;
    const int r = gid >> 6;
    const int d = (gid & 63) * 4;
    const int b = r >> 10;
    const int t = r & (TDIM - 1);
    const float tv = (t < con_lens[b]) ? 1.f : 0.f;
    float4 c = *(const float4*)&ctx[((size_t)t * BDIM + b) * DDIM + d];
    float4 q = *(const float4*)&g_q2c[b * DDIM + d];
    float4 o;
    o.x = c.x * q.x * tv; o.y = c.y * q.y * tv;
    o.z = c.z * q.z * tv; o.w = c.w * q.w * tv;
    *(float4*)&G[(size_t)r * (4 * DDIM) + 3 * DDIM + d] = o;
}

extern "C" void kernel_launch(void* const* d_in, const int* in_sizes, int n_in,
                              void* d_out, int out_size)
{
    const float* ctx = (const float*)d_in[0];
    const float* qst = (const float*)d_in[1];
    const int*   cl  = (const int*)d_in[2];
    const int*   ql  = (const int*)d_in[3];
    const float* aw  = (const float*)d_in[4];
    float* G = (float*)d_out;

    const size_t smem1 = SMEM_FLOATS * sizeof(float);
    cudaFuncSetAttribute(bidaf_k1, cudaFuncAttributeMaxDynamicSharedMemorySize, (int)smem1);

    dim3 g1(TDIM / TT, BDIM);
    bidaf_k1<<<g1, 256, smem1>>>(ctx, qst, cl, ql, aw, G);
    bidaf_k2<<<BDIM, 256>>>(ctx);
    bidaf_k3<<<(BDIM * TDIM * DDIM / 4) / 256, 256>>>(ctx, cl, G);
}

// round 2
// speedup vs baseline: 1.0678x; 1.0678x over previous
#include <cuda_runtime.h>
#include <cstdint>

#define TDIM 1024
#define JDIM 128
#define BDIM 32
#define DDIM 256
#define TT   64
#define VNEG -1e30f

typedef unsigned long long u64;

__device__ __forceinline__ u64 ffma2(u64 a, u64 b, u64 c) {
    u64 d; asm("fma.rn.f32x2 %0,%1,%2,%3;" : "=l"(d) : "l"(a), "l"(b), "l"(c)); return d;
}
__device__ __forceinline__ float2 unpk2(u64 a) {
    float2 f; asm("mov.b64 {%0,%1},%2;" : "=f"(f.x), "=f"(f.y) : "l"(a)); return f;
}
__device__ __forceinline__ u64 pk2(float x, float y) {
    u64 d; asm("mov.b64 %0,{%1,%2};" : "=l"(d) : "f"(x), "f"(y)); return d;
}

// scratch (static device arrays — no allocation)
__device__ float g_mbuf[BDIM * TDIM];
__device__ float g_q2c[BDIM * DDIM];

// shared memory layout (in floats)
#define OFF_QS    0                      // 128*256 swizzled question
#define OFF_CWS   (128*256)              // union: cws 64*260  /  pT 128*68
#define OFF_SWC   (OFF_CWS + 64*260)
#define OFF_SWQ   (OFF_SWC + 256)
#define OFF_SWCQ  (OFF_SWQ + 256)
#define OFF_QPROJ (OFF_SWCQ + 256)
#define OFF_CPROJ (OFF_QPROJ + 128)
#define SMEM_FLOATS (OFF_CPROJ + 64)

__global__ __launch_bounds__(256, 1)
void bidaf_k1(const float* __restrict__ ctx, const float* __restrict__ qst,
              const int* __restrict__ con_lens, const int* __restrict__ qu_lens,
              const float* __restrict__ att_w, float* __restrict__ G)
{
    extern __shared__ float sm[];
    float* qs    = sm + OFF_QS;
    float* cws   = sm + OFF_CWS;
    float* pT    = cws;                 // reuse after cross-matmul
    float* swc   = sm + OFF_SWC;
    float* swq   = sm + OFF_SWQ;
    float* swcq  = sm + OFF_SWCQ;
    float* qproj = sm + OFF_QPROJ;
    float* cproj = sm + OFF_CPROJ;

    const int tid  = threadIdx.x;
    const int b    = blockIdx.y;
    const int t0   = blockIdx.x * TT;
    const int clen = con_lens[b];
    const int qlen = qu_lens[b];

    // weights into smem
    swc[tid]  = att_w[tid];
    swq[tid]  = att_w[DDIM + tid];
    swcq[tid] = att_w[2 * DDIM + tid];
    __syncthreads();

    const int sub   = tid & 3;
    const int rowid = tid >> 2;

    // ---- load question tile (swizzled) + qproj -------------------------
    #pragma unroll
    for (int pass = 0; pass < 2; ++pass) {
        const int j = pass * 64 + rowid;
        const float* src = qst + ((size_t)j * BDIM + b) * DDIM;
        const int xr = j & 28;
        float qp = 0.f;
        #pragma unroll
        for (int i = 0; i < 16; ++i) {
            const int d = i * 16 + sub * 4;
            float4 v = *(const float4*)(src + d);
            *(float4*)&qs[j * DDIM + (d ^ xr)] = v;
            qp += v.x * swq[d] + v.y * swq[d + 1] + v.z * swq[d + 2] + v.w * swq[d + 3];
        }
        qp += __shfl_xor_sync(0xffffffffu, qp, 1);
        qp += __shfl_xor_sync(0xffffffffu, qp, 2);
        if (sub == 0) qproj[j] = qp;
    }

    // ---- load context tile -> cw = ctx*w_cq, cproj --------------------
    {
        const int tl = rowid;
        const int t  = t0 + tl;
        const float* src = ctx + ((size_t)t * BDIM + b) * DDIM;
        float cp = 0.f;
        #pragma unroll
        for (int i = 0; i < 16; ++i) {
            const int d = i * 16 + sub * 4;
            float4 v = *(const float4*)(src + d);
            float4 w = *(const float4*)&swcq[d];
            float4 cv;
            cv.x = v.x * w.x; cv.y = v.y * w.y; cv.z = v.z * w.z; cv.w = v.w * w.w;
            *(float4*)&cws[tl * 260 + d] = cv;
            float4 wc = *(const float4*)&swc[d];
            cp += v.x * wc.x + v.y * wc.y + v.z * wc.z + v.w * wc.w;
        }
        cp += __shfl_xor_sync(0xffffffffu, cp, 1);
        cp += __shfl_xor_sync(0xffffffffu, cp, 2);
        if (sub == 0) cproj[tl] = cp;
    }
    __syncthreads();

    const int tx  = tid & 15;
    const int ty  = tid >> 4;
    const int j0  = tx * 4;
    const int xr0 = j0 & 28;

    // ---- cross matmul: S[4t][8j], packed f32x2 over d -------------------
    // acc2 lanes hold (even-d, odd-d) partial sums; folded after the loop.
    u64 acc2[4][8];
    #pragma unroll
    for (int i = 0; i < 4; ++i)
        #pragma unroll
        for (int jj = 0; jj < 8; ++jj) acc2[i][jj] = 0ull;

    #pragma unroll 2
    for (int d = 0; d < DDIM; d += 4) {
        ulonglong2 qv[8];
        #pragma unroll
        for (int jj = 0; jj < 4; ++jj) {
            qv[jj]     = *(const ulonglong2*)&qs[(j0 + jj) * DDIM + (d ^ xr0)];
            qv[4 + jj] = *(const ulonglong2*)&qs[(j0 + 64 + jj) * DDIM + (d ^ xr0)];
        }
        ulonglong2 cv[4];
        #pragma unroll
        for (int i = 0; i < 4; ++i)
            cv[i] = *(const ulonglong2*)&cws[(ty * 4 + i) * 260 + d];
        #pragma unroll
        for (int i = 0; i < 4; ++i)
            #pragma unroll
            for (int jj = 0; jj < 8; ++jj) {
                acc2[i][jj] = ffma2(cv[i].x, qv[jj].x, acc2[i][jj]);
                acc2[i][jj] = ffma2(cv[i].y, qv[jj].y, acc2[i][jj]);
            }
    }

    // ---- masked softmax over j (16-lane shfl reduce) --------------------
    float pr[4][8];
    #pragma unroll
    for (int i = 0; i < 4; ++i) {
        const int t = t0 + ty * 4 + i;
        const bool tval = t < clen;
        const float cpv = cproj[ty * 4 + i];
        float s[8];
        #pragma unroll
        for (int jj = 0; jj < 8; ++jj) {
            const int j = (jj < 4) ? (j0 + jj) : (j0 + 60 + jj);
            float2 av = unpk2(acc2[i][jj]);
            const float sv = cpv + qproj[j] + (av.x + av.y);
            s[jj] = (tval && (j < qlen)) ? sv : VNEG;
        }
        float mx = s[0];
        #pragma unroll
        for (int jj = 1; jj < 8; ++jj) mx = fmaxf(mx, s[jj]);
        #pragma unroll
        for (int o = 1; o < 16; o <<= 1) mx = fmaxf(mx, __shfl_xor_sync(0xffffffffu, mx, o));
        float sum = 0.f;
        #pragma unroll
        for (int jj = 0; jj < 8; ++jj) { s[jj] = __expf(s[jj] - mx); sum += s[jj]; }
        #pragma unroll
        for (int o = 1; o < 16; o <<= 1) sum += __shfl_xor_sync(0xffffffffu, sum, o);
        const float inv = 1.f / sum;
        #pragma unroll
        for (int jj = 0; jj < 8; ++jj) pr[i][jj] = s[jj] * inv;
        if (tx == 0) g_mbuf[b * TDIM + t] = mx;
    }
    __syncthreads();   // all cws reads complete before pT overwrite

    // ---- stage P transposed: pT[j][t] ----------------------------------
    #pragma unroll
    for (int jj = 0; jj < 8; ++jj) {
        const int j = (jj < 4) ? (j0 + jj) : (j0 + 60 + jj);
        #pragma unroll
        for (int i = 0; i < 4; ++i)
            pT[j * 68 + ty * 4 + i] = pr[i][jj];
    }
    __syncthreads();

    // ---- second matmul: c2q[4t][16d] = P @ Q, packed f32x2 over output d
    u64 c2b[4][8];
    #pragma unroll
    for (int i = 0; i < 4; ++i)
        #pragma unroll
        for (int k = 0; k < 8; ++k) c2b[i][k] = 0ull;

    const int d0 = tx * 4;
    #pragma unroll 2
    for (int j = 0; j < JDIM; ++j) {
        float4 pv = *(const float4*)&pT[j * 68 + ty * 4];
        const int xr = j & 28;
        ulonglong2 qv2[4];
        #pragma unroll
        for (int k = 0; k < 4; ++k)
            qv2[k] = *(const ulonglong2*)&qs[j * DDIM + ((d0 + 64 * k) ^ xr)];
        u64 pa2[4];
        pa2[0] = pk2(pv.x, pv.x); pa2[1] = pk2(pv.y, pv.y);
        pa2[2] = pk2(pv.z, pv.z); pa2[3] = pk2(pv.w, pv.w);
        #pragma unroll
        for (int i = 0; i < 4; ++i)
            #pragma unroll
            for (int k = 0; k < 4; ++k) {
                c2b[i][2 * k]     = ffma2(pa2[i], qv2[k].x, c2b[i][2 * k]);
                c2b[i][2 * k + 1] = ffma2(pa2[i], qv2[k].y, c2b[i][2 * k + 1]);
            }
    }

    // ---- epilogue: G[:, 0:768] ------------------------------------------
    #pragma unroll
    for (int i = 0; i < 4; ++i) {
        const int t = t0 + ty * 4 + i;
        const float tv = (t < clen) ? 1.f : 0.f;
        const float* crow = ctx + ((size_t)t * BDIM + b) * DDIM;
        float* grow = G + ((size_t)b * TDIM + t) * (4 * DDIM);
        #pragma unroll
        for (int k = 0; k < 4; ++k) {
            const int d = d0 + 64 * k;
            float4 cvv = *(const float4*)(crow + d);
            float2 f0 = unpk2(c2b[i][2 * k]);
            float2 f1 = unpk2(c2b[i][2 * k + 1]);
            float4 aq;
            aq.x = f0.x; aq.y = f0.y; aq.z = f1.x; aq.w = f1.y;
            float4 o0, o1, o2;
            o0.x = cvv.x * tv;        o0.y = cvv.y * tv;        o0.z = cvv.z * tv;        o0.w = cvv.w * tv;
            o1.x = aq.x * tv;         o1.y = aq.y * tv;         o1.z = aq.z * tv;         o1.w = aq.w * tv;
            o2.x = cvv.x * aq.x * tv; o2.y = cvv.y * aq.y * tv; o2.z = cvv.z * aq.z * tv; o2.w = cvv.w * aq.w * tv;
            *(float4*)(grow + d)        = o0;
            *(float4*)(grow + 256 + d)  = o1;
            *(float4*)(grow + 512 + d)  = o2;
        }
    }
}

// ---- kernel 2: value = softmax_t(m); q2c_vec = value . context ----------
__global__ __launch_bounds__(256, 1)
void bidaf_k2(const float* __restrict__ ctx)
{
    __shared__ float vbuf[TDIM];
    __shared__ float red[8];
    __shared__ float4 pb[4][64];
    const int b = blockIdx.x;
    const int tid = threadIdx.x;
    const int lane = tid & 31, wid = tid >> 5;

    float mv[4];
    float mx = -3.4e38f;
    #pragma unroll
    for (int r = 0; r < 4; ++r) {
        mv[r] = g_mbuf[b * TDIM + r * 256 + tid];
        mx = fmaxf(mx, mv[r]);
    }
    #pragma unroll
    for (int o = 16; o > 0; o >>= 1) mx = fmaxf(mx, __shfl_xor_sync(0xffffffffu, mx, o));
    if (lane == 0) red[wid] = mx;
    __syncthreads();
    mx = red[0];
    #pragma unroll
    for (int w = 1; w < 8; ++w) mx = fmaxf(mx, red[w]);

    float sum = 0.f;
    #pragma unroll
    for (int r = 0; r < 4; ++r) {
        float e = __expf(mv[r] - mx);
        vbuf[r * 256 + tid] = e;
        sum += e;
    }
    #pragma unroll
    for (int o = 16; o > 0; o >>= 1) sum += __shfl_xor_sync(0xffffffffu, sum, o);
    __syncthreads();
    if (lane == 0) red[wid] = sum;
    __syncthreads();
    float tot = 0.f;
    #pragma unroll
    for (int w = 0; w < 8; ++w) tot += red[w];
    const float inv = 1.f / tot;

    const int dq = (tid & 63) * 4;
    const int chunk = tid >> 6;
    float4 acc = {0.f, 0.f, 0.f, 0.f};
    for (int tt = chunk * 256; tt < chunk * 256 + 256; ++tt) {
        const float v = vbuf[tt];
        float4 c = *(const float4*)&ctx[((size_t)tt * BDIM + b) * DDIM + dq];
        acc.x += v * c.x; acc.y += v * c.y; acc.z += v * c.z; acc.w += v * c.w;
    }
    pb[chunk][tid & 63] = acc;
    __syncthreads();
    if (chunk == 0) {
        float4 s0 = pb[0][tid], s1 = pb[1][tid], s2 = pb[2][tid], s3 = pb[3][tid];
        float4 s;
        s.x = (s0.x + s1.x + s2.x + s3.x) * inv;
        s.y = (s0.y + s1.y + s2.y + s3.y) * inv;
        s.z = (s0.z + s1.z + s2.z + s3.z) * inv;
        s.w = (s0.w + s1.w + s2.w + s3.w) * inv;
        *(float4*)&g_q2c[b * DDIM + dq] = s;
    }
}

// ---- kernel 3: G[:, 768:1024] = ctx * q2c * t_valid ----------------------
__global__ void bidaf_k3(const float* __restrict__ ctx, const int* __restrict__ con_lens,
                         float* __restrict__ G)
{
    const int gid = blockIdx.x * 256 + threadIdx.x;
    const int r = gid >> 6;
    const int d = (gid & 63) * 4;
    const int b = r >> 10;
    const int t = r & (TDIM - 1);
    const float tv = (t < con_lens[b]) ? 1.f : 0.f;
    float4 c = *(const float4*)&ctx[((size_t)t * BDIM + b) * DDIM + d];
    float4 q = *(const float4*)&g_q2c[b * DDIM + d];
    float4 o;
    o.x = c.x * q.x * tv; o.y = c.y * q.y * tv;
    o.z = c.z * q.z * tv; o.w = c.w * q.w * tv;
    *(float4*)&G[(size_t)r * (4 * DDIM) + 3 * DDIM + d] = o;
}

extern "C" void kernel_launch(void* const* d_in, const int* in_sizes, int n_in,
                              void* d_out, int out_size)
{
    const float* ctx = (const float*)d_in[0];
    const float* qst = (const float*)d_in[1];
    const int*   cl  = (const int*)d_in[2];
    const int*   ql  = (const int*)d_in[3];
    const float* aw  = (const float*)d_in[4];
    float* G = (float*)d_out;

    const size_t smem1 = SMEM_FLOATS * sizeof(float);
    cudaFuncSetAttribute(bidaf_k1, cudaFuncAttributeMaxDynamicSharedMemorySize, (int)smem1);

    dim3 g1(TDIM / TT, BDIM);
    bidaf_k1<<<g1, 256, smem1>>>(ctx, qst, cl, ql, aw, G);
    bidaf_k2<<<BDIM, 256>>>(ctx);
    bidaf_k3<<<(BDIM * TDIM * DDIM / 4) / 256, 256>>>(ctx, cl, G);
}

// round 4
// speedup vs baseline: 1.6478x; 1.5431x over previous
#include <cuda_runtime.h>
#include <cuda_bf16.h>
#include <cstdint>

#define TDIM 1024
#define JDIM 128
#define BDIM 32
#define DDIM 256
#define VNEG -1e30f

// ---------------- scratch ----------------
__device__ float g_mbuf[BDIM * TDIM];
__device__ float g_q2c[BDIM * DDIM];
__device__ float g_value[BDIM * TDIM];

// ---------------- PTX helpers (baseline sm_80 features only) ----------------
__device__ __forceinline__ void ldsm4(uint32_t* r, uint32_t addr) {
    asm volatile("ldmatrix.sync.aligned.m8n8.x4.shared.b16 {%0,%1,%2,%3}, [%4];"
        : "=r"(r[0]), "=r"(r[1]), "=r"(r[2]), "=r"(r[3]) : "r"(addr));
}
__device__ __forceinline__ void ldsm4t(uint32_t* r, uint32_t addr) {
    asm volatile("ldmatrix.sync.aligned.m8n8.x4.trans.shared.b16 {%0,%1,%2,%3}, [%4];"
        : "=r"(r[0]), "=r"(r[1]), "=r"(r[2]), "=r"(r[3]) : "r"(addr));
}
__device__ __forceinline__ void mma_bf16(float* d, const uint32_t* a, uint32_t b0, uint32_t b1) {
    asm volatile("mma.sync.aligned.m16n8k16.row.col.f32.bf16.bf16.f32 "
        "{%0,%1,%2,%3}, {%4,%5,%6,%7}, {%8,%9}, {%0,%1,%2,%3};"
        : "+f"(d[0]), "+f"(d[1]), "+f"(d[2]), "+f"(d[3])
        : "r"(a[0]), "r"(a[1]), "r"(a[2]), "r"(a[3]), "r"(b0), "r"(b1));
}
__device__ __forceinline__ uint32_t smem_to_u32(const void* p) {
    uint32_t a;
    asm("{ .reg .u64 t; cvta.to.shared.u64 t, %1; cvt.u32.u64 %0, t; }" : "=r"(a) : "l"(p));
    return a;
}
__device__ __forceinline__ uint32_t packbf(float e0, float e1) {
    __nv_bfloat162 h = __floats2bfloat162_rn(e0, e1);   // .x -> low 16 bits
    return *reinterpret_cast<uint32_t*>(&h);
}
__device__ __forceinline__ float bres(float x) {        // x - bf16(x)
    return x - __bfloat162float(__float2bfloat16(x));
}

// swizzled byte offsets (XOR within 128B blocks, spreads 8 rows over 8 16B slots)
__device__ __forceinline__ uint32_t sw512(int row, int colb) {   // 512B rows (Q: 256 bf16)
    return (uint32_t)(row * 512 + (colb & ~127) + ((colb & 127) ^ ((row & 7) << 4)));
}
__device__ __forceinline__ uint32_t sw256(int row, int colb) {   // 256B rows (cw chunk: 128 bf16)
    return (uint32_t)(row * 256 + (colb & ~127) + ((colb & 127) ^ ((row & 7) << 4)));
}

// dynamic smem layout (bytes)
#define QHI_OFF  0
#define QLO_OFF  65536
#define CWHI_OFF 131072
#define CWLO_OFF 163840
#define SMEM_DYN 196608

// split 8 floats -> hi uint4 / lo uint4
__device__ __forceinline__ void split8(const float* v, uint4& H, uint4& L) {
    __nv_bfloat162 h0 = __floats2bfloat162_rn(v[0], v[1]);
    __nv_bfloat162 h1 = __floats2bfloat162_rn(v[2], v[3]);
    __nv_bfloat162 h2 = __floats2bfloat162_rn(v[4], v[5]);
    __nv_bfloat162 h3 = __floats2bfloat162_rn(v[6], v[7]);
    float2 f0 = __bfloat1622float2(h0), f1 = __bfloat1622float2(h1);
    float2 f2 = __bfloat1622float2(h2), f3 = __bfloat1622float2(h3);
    __nv_bfloat162 l0 = __floats2bfloat162_rn(v[0] - f0.x, v[1] - f0.y);
    __nv_bfloat162 l1 = __floats2bfloat162_rn(v[2] - f1.x, v[3] - f1.y);
    __nv_bfloat162 l2 = __floats2bfloat162_rn(v[4] - f2.x, v[5] - f2.y);
    __nv_bfloat162 l3 = __floats2bfloat162_rn(v[6] - f3.x, v[7] - f3.y);
    H = make_uint4(*(uint32_t*)&h0, *(uint32_t*)&h1, *(uint32_t*)&h2, *(uint32_t*)&h3);
    L = make_uint4(*(uint32_t*)&l0, *(uint32_t*)&l1, *(uint32_t*)&l2, *(uint32_t*)&l3);
}

__global__ __launch_bounds__(256, 1)
void bidaf_k1_mma(const float* __restrict__ ctx, const float* __restrict__ qst,
                  const int* __restrict__ con_lens, const int* __restrict__ qu_lens,
                  const float* __restrict__ att_w, float* __restrict__ G)
{
    extern __shared__ char U[];
    __shared__ float s_wc[256], s_wq[256], s_wcq[256];
    __shared__ float s_qproj[128], s_cproj[128];

    const uint32_t ub = smem_to_u32(U);
    const int tid  = threadIdx.x;
    const int lane = tid & 31;
    const int warp = tid >> 5;
    const int b    = blockIdx.y;
    const int t0   = blockIdx.x * 128;
    const int clen = con_lens[b];
    const int qlen = qu_lens[b];

    s_wc[tid]  = att_w[tid];
    s_wq[tid]  = att_w[256 + tid];
    s_wcq[tid] = att_w[512 + tid];
    __syncthreads();

    // ---------------- stage Q [128j x 256d] split bf16 + qproj ----------------
    {
        const int j  = tid >> 1;
        const int hf = (tid & 1) * 128;
        const float* src = qst + ((size_t)j * BDIM + b) * DDIM + hf;
        float qp = 0.f;
        #pragma unroll
        for (int i = 0; i < 16; ++i) {
            float v[8];
            *(float4*)(v)     = *(const float4*)(src + i * 8);
            *(float4*)(v + 4) = *(const float4*)(src + i * 8 + 4);
            const float* w = s_wq + hf + i * 8;
            #pragma unroll
            for (int e = 0; e < 8; ++e) qp += v[e] * w[e];
            uint4 H, L;
            split8(v, H, L);
            const uint32_t off = sw512(j, hf * 2 + i * 16);
            *(uint4*)(U + QHI_OFF + off) = H;
            *(uint4*)(U + QLO_OFF + off) = L;
        }
        qp += __shfl_xor_sync(0xffffffffu, qp, 1);
        if ((tid & 1) == 0) s_qproj[j] = qp;
    }

    // ---------------- cw chunk stage lambda-ish (macro via loop) --------------
    float cp_acc = 0.f;
    // stage chunk 0 now
    {
        const int r  = tid >> 1;
        const int hf = (tid & 1) * 64;
        const float* src = ctx + ((size_t)(t0 + r) * BDIM + b) * DDIM + hf;
        #pragma unroll
        for (int i = 0; i < 8; ++i) {
            float v[8];
            *(float4*)(v)     = *(const float4*)(src + i * 8);
            *(float4*)(v + 4) = *(const float4*)(src + i * 8 + 4);
            const float* wc  = s_wc  + hf + i * 8;
            const float* wcq = s_wcq + hf + i * 8;
            float m[8];
            #pragma unroll
            for (int e = 0; e < 8; ++e) { cp_acc += v[e] * wc[e]; m[e] = v[e] * wcq[e]; }
            uint4 H, L;
            split8(m, H, L);
            const uint32_t off = sw256(r, hf * 2 + i * 16);
            *(uint4*)(U + CWHI_OFF + off) = H;
            *(uint4*)(U + CWLO_OFF + off) = L;
        }
    }

    // fragment address components
    const int rb = warp * 16;
    const uint32_t a_row  = (uint32_t)(rb + (lane & 15));
    const uint32_t a_cb   = (uint32_t)((lane >> 4) * 16);
    const uint32_t b1_row = (uint32_t)(((lane >> 4) << 3) + (lane & 7));   // GEMM1 B
    const uint32_t b1_cb  = (uint32_t)(((lane >> 3) & 1) * 16);
    const uint32_t b2_row = (uint32_t)(lane & 15);                          // GEMM2 B (trans)
    const uint32_t b2_cb  = (uint32_t)((lane >> 4) * 16);

    float acc[16][4];
    #pragma unroll
    for (int n = 0; n < 16; ++n)
        #pragma unroll
        for (int e = 0; e < 4; ++e) acc[n][e] = 0.f;

    // ---------------- GEMM1: S = cw . Q^T, k chunked 2x128 --------------------
    #pragma unroll 1
    for (int c = 0; c < 2; ++c) {
        if (c == 1) {
            __syncthreads();   // chunk0 mma done reading cw
            const int r  = tid >> 1;
            const int hf = (tid & 1) * 64;
            const float* src = ctx + ((size_t)(t0 + r) * BDIM + b) * DDIM + 128 + hf;
            #pragma unroll
            for (int i = 0; i < 8; ++i) {
                float v[8];
                *(float4*)(v)     = *(const float4*)(src + i * 8);
                *(float4*)(v + 4) = *(const float4*)(src + i * 8 + 4);
                const float* wc  = s_wc  + 128 + hf + i * 8;
                const float* wcq = s_wcq + 128 + hf + i * 8;
                float m[8];
                #pragma unroll
                for (int e = 0; e < 8; ++e) { cp_acc += v[e] * wc[e]; m[e] = v[e] * wcq[e]; }
                uint4 H, L;
                split8(m, H, L);
                const uint32_t off = sw256(r, hf * 2 + i * 16);
                *(uint4*)(U + CWHI_OFF + off) = H;
                *(uint4*)(U + CWLO_OFF + off) = L;
            }
            float cpr = cp_acc + __shfl_xor_sync(0xffffffffu, cp_acc, 1);
            if ((tid & 1) == 0) s_cproj[tid >> 1] = cpr;
        }
        __syncthreads();

        #pragma unroll 1
        for (int pass = 0; pass < 3; ++pass) {
            const uint32_t Ab = ub + ((pass < 2) ? CWHI_OFF : CWLO_OFF);
            const uint32_t Bb = ub + ((pass == 1) ? QLO_OFF : QHI_OFF);
            #pragma unroll
            for (int ks = 0; ks < 8; ++ks) {
                uint32_t a[4];
                ldsm4(a, Ab + sw256((int)a_row, ks * 32 + (int)a_cb));
                #pragma unroll
                for (int nb2 = 0; nb2 < 8; ++nb2) {
                    uint32_t bf[4];
                    ldsm4(bf, Bb + sw512(nb2 * 16 + (int)b1_row, c * 256 + ks * 32 + (int)b1_cb));
                    mma_bf16(acc[nb2 * 2],     a, bf[0], bf[1]);
                    mma_bf16(acc[nb2 * 2 + 1], a, bf[2], bf[3]);
                }
            }
        }
    }
    __syncthreads();

    // ---------------- softmax over j in registers -----------------------------
    const int r0 = rb + (lane >> 2);
    const int r1 = r0 + 8;
    const float cpv0 = s_cproj[r0], cpv1 = s_cproj[r1];
    const bool tval0 = (t0 + r0) < clen;
    const bool tval1 = (t0 + r1) < clen;

    float mx0 = -3.4e38f, mx1 = -3.4e38f;
    #pragma unroll
    for (int nb = 0; nb < 16; ++nb) {
        const int j0 = nb * 8 + (lane & 3) * 2;
        const float2 qp = *(const float2*)&s_qproj[j0];
        const bool jv0 = j0 < qlen, jv1 = (j0 + 1) < qlen;
        float s0 = (tval0 && jv0) ? acc[nb][0] + cpv0 + qp.x : VNEG;
        float s1 = (tval0 && jv1) ? acc[nb][1] + cpv0 + qp.y : VNEG;
        float s2 = (tval1 && jv0) ? acc[nb][2] + cpv1 + qp.x : VNEG;
        float s3 = (tval1 && jv1) ? acc[nb][3] + cpv1 + qp.y : VNEG;
        acc[nb][0] = s0; acc[nb][1] = s1; acc[nb][2] = s2; acc[nb][3] = s3;
        mx0 = fmaxf(mx0, fmaxf(s0, s1));
        mx1 = fmaxf(mx1, fmaxf(s2, s3));
    }
    mx0 = fmaxf(mx0, __shfl_xor_sync(0xffffffffu, mx0, 1));
    mx0 = fmaxf(mx0, __shfl_xor_sync(0xffffffffu, mx0, 2));
    mx1 = fmaxf(mx1, __shfl_xor_sync(0xffffffffu, mx1, 1));
    mx1 = fmaxf(mx1, __shfl_xor_sync(0xffffffffu, mx1, 2));

    float sm0 = 0.f, sm1 = 0.f;
    #pragma unroll
    for (int nb = 0; nb < 16; ++nb) {
        acc[nb][0] = __expf(acc[nb][0] - mx0); sm0 += acc[nb][0];
        acc[nb][1] = __expf(acc[nb][1] - mx0); sm0 += acc[nb][1];
        acc[nb][2] = __expf(acc[nb][2] - mx1); sm1 += acc[nb][2];
        acc[nb][3] = __expf(acc[nb][3] - mx1); sm1 += acc[nb][3];
    }
    sm0 += __shfl_xor_sync(0xffffffffu, sm0, 1);
    sm0 += __shfl_xor_sync(0xffffffffu, sm0, 2);
    sm1 += __shfl_xor_sync(0xffffffffu, sm1, 1);
    sm1 += __shfl_xor_sync(0xffffffffu, sm1, 2);
    const float iv0 = 1.f / sm0, iv1 = 1.f / sm1;

    if ((lane & 3) == 0) {
        g_mbuf[b * TDIM + t0 + r0] = mx0;
        g_mbuf[b * TDIM + t0 + r1] = mx1;
    }

    // ---------------- pack P into A-fragments (hi/lo) -------------------------
    uint32_t Ah[8][4], Al[8][4];
    #pragma unroll
    for (int ks = 0; ks < 8; ++ks) {
        float p00 = acc[2 * ks][0] * iv0,     p01 = acc[2 * ks][1] * iv0;
        float p10 = acc[2 * ks][2] * iv1,     p11 = acc[2 * ks][3] * iv1;
        float p20 = acc[2 * ks + 1][0] * iv0, p21 = acc[2 * ks + 1][1] * iv0;
        float p30 = acc[2 * ks + 1][2] * iv1, p31 = acc[2 * ks + 1][3] * iv1;
        Ah[ks][0] = packbf(p00, p01); Al[ks][0] = packbf(bres(p00), bres(p01));
        Ah[ks][1] = packbf(p10, p11); Al[ks][1] = packbf(bres(p10), bres(p11));
        Ah[ks][2] = packbf(p20, p21); Al[ks][2] = packbf(bres(p20), bres(p21));
        Ah[ks][3] = packbf(p30, p31); Al[ks][3] = packbf(bres(p30), bres(p31));
    }

    // ---------------- GEMM2: c2q = P . Q, two 128-d halves --------------------
    const float tv0 = tval0 ? 1.f : 0.f;
    const float tv1 = tval1 ? 1.f : 0.f;
    const float* crow0 = ctx + ((size_t)(t0 + r0) * BDIM + b) * DDIM;
    const float* crow1 = ctx + ((size_t)(t0 + r1) * BDIM + b) * DDIM;
    float* grow0 = G + ((size_t)b * TDIM + t0 + r0) * (4 * DDIM);
    float* grow1 = G + ((size_t)b * TDIM + t0 + r1) * (4 * DDIM);

    #pragma unroll 1
    for (int h = 0; h < 2; ++h) {
        #pragma unroll
        for (int n = 0; n < 16; ++n)
            #pragma unroll
            for (int e = 0; e < 4; ++e) acc[n][e] = 0.f;

        #pragma unroll 1
        for (int pass = 0; pass < 3; ++pass) {
            const uint32_t Bb = ub + ((pass == 1) ? QLO_OFF : QHI_OFF);
            const uint32_t (*A)[4] = (pass < 2) ? Ah : Al;
            #pragma unroll
            for (int ks = 0; ks < 8; ++ks) {
                #pragma unroll
                for (int nb2 = 0; nb2 < 8; ++nb2) {
                    uint32_t bf[4];
                    ldsm4t(bf, Bb + sw512(ks * 16 + (int)b2_row, h * 256 + nb2 * 32 + (int)b2_cb));
                    mma_bf16(acc[nb2 * 2],     A[ks], bf[0], bf[1]);
                    mma_bf16(acc[nb2 * 2 + 1], A[ks], bf[2], bf[3]);
                }
            }
        }

        // epilogue for this d-half: G cols [0,768)
        #pragma unroll
        for (int nb = 0; nb < 16; ++nb) {
            const int d = h * 128 + nb * 8 + (lane & 3) * 2;
            float2 c0 = *(const float2*)(crow0 + d);
            float2 c1 = *(const float2*)(crow1 + d);
            float2 q0 = make_float2(acc[nb][0], acc[nb][1]);
            float2 q1 = make_float2(acc[nb][2], acc[nb][3]);
            *(float2*)(grow0 + d)       = make_float2(c0.x * tv0, c0.y * tv0);
            *(float2*)(grow0 + 256 + d) = make_float2(q0.x * tv0, q0.y * tv0);
            *(float2*)(grow0 + 512 + d) = make_float2(c0.x * q0.x * tv0, c0.y * q0.y * tv0);
            *(float2*)(grow1 + d)       = make_float2(c1.x * tv1, c1.y * tv1);
            *(float2*)(grow1 + 256 + d) = make_float2(q1.x * tv1, q1.y * tv1);
            *(float2*)(grow1 + 512 + d) = make_float2(c1.x * q1.x * tv1, c1.y * q1.y * tv1);
        }
    }
}

// ---- k2a: value = softmax_t(m) -> g_value; zero g_q2c ----
__global__ __launch_bounds__(256, 1)
void bidaf_k2a()
{
    __shared__ float red[8];
    const int b = blockIdx.x;
    const int tid = threadIdx.x;
    const int lane = tid & 31, wid = tid >> 5;

    float mv[4];
    float mx = -3.4e38f;
    #pragma unroll
    for (int r = 0; r < 4; ++r) {
        mv[r] = g_mbuf[b * TDIM + r * 256 + tid];
        mx = fmaxf(mx, mv[r]);
    }
    #pragma unroll
    for (int o = 16; o > 0; o >>= 1) mx = fmaxf(mx, __shfl_xor_sync(0xffffffffu, mx, o));
    if (lane == 0) red[wid] = mx;
    __syncthreads();
    mx = red[0];
    #pragma unroll
    for (int w = 1; w < 8; ++w) mx = fmaxf(mx, red[w]);

    float e[4], sum = 0.f;
    #pragma unroll
    for (int r = 0; r < 4; ++r) { e[r] = __expf(mv[r] - mx); sum += e[r]; }
    #pragma unroll
    for (int o = 16; o > 0; o >>= 1) sum += __shfl_xor_sync(0xffffffffu, sum, o);
    __syncthreads();
    if (lane == 0) red[wid] = sum;
    __syncthreads();
    float tot = 0.f;
    #pragma unroll
    for (int w = 0; w < 8; ++w) tot += red[w];
    const float inv = 1.f / tot;
    #pragma unroll
    for (int r = 0; r < 4; ++r) g_value[b * TDIM + r * 256 + tid] = e[r] * inv;
    if (tid < 64) {
        #pragma unroll
        for (int k = 0; k < 4; ++k) g_q2c[b * DDIM + k * 64 + tid] = 0.f;
    }
}

// ---- k2b: q2c partial sums (grid 8x32) ----
__global__ __launch_bounds__(256, 1)
void bidaf_k2b(const float* __restrict__ ctx)
{
    __shared__ float4 pb[4][64];
    const int b = blockIdx.y;
    const int tc0 = blockIdx.x * 128;
    const int tid = threadIdx.x;
    const int dq = (tid & 63) * 4;
    const int sub = tid >> 6;

    float4 acc = {0.f, 0.f, 0.f, 0.f};
    #pragma unroll 4
    for (int tt = tc0 + sub * 32; tt < tc0 + sub * 32 + 32; ++tt) {
        const float v = g_value[b * TDIM + tt];
        float4 c = *(const float4*)&ctx[((size_t)tt * BDIM + b) * DDIM + dq];
        acc.x += v * c.x; acc.y += v * c.y; acc.z += v * c.z; acc.w += v * c.w;
    }
    pb[sub][tid & 63] = acc;
    __syncthreads();
    if (sub == 0) {
        float4 s0 = pb[0][tid], s1 = pb[1][tid], s2 = pb[2][tid], s3 = pb[3][tid];
        atomicAdd(&g_q2c[b * DDIM + dq],     s0.x + s1.x + s2.x + s3.x);
        atomicAdd(&g_q2c[b * DDIM + dq + 1], s0.y + s1.y + s2.y + s3.y);
        atomicAdd(&g_q2c[b * DDIM + dq + 2], s0.z + s1.z + s2.z + s3.z);
        atomicAdd(&g_q2c[b * DDIM + dq + 3], s0.w + s1.w + s2.w + s3.w);
    }
}

// ---- k3: G[:, 768:1024] = ctx * q2c * t_valid ----
__global__ void bidaf_k3(const float* __restrict__ ctx, const int* __restrict__ con_lens,
                         float* __restrict__ G)
{
    const int gid = blockIdx.x * 256 + threadIdx.x;
    const int r = gid >> 6;
    const int d = (gid & 63) * 4;
    const int b = r >> 10;
    const int t = r & (TDIM - 1);
    const float tv = (t < con_lens[b]) ? 1.f : 0.f;
    float4 c = *(const float4*)&ctx[((size_t)t * BDIM + b) * DDIM + d];
    float4 q = *(const float4*)&g_q2c[b * DDIM + d];
    float4 o;
    o.x = c.x * q.x * tv; o.y = c.y * q.y * tv;
    o.z = c.z * q.z * tv; o.w = c.w * q.w * tv;
    *(float4*)&G[(size_t)r * (4 * DDIM) + 3 * DDIM + d] = o;
}

extern "C" void kernel_launch(void* const* d_in, const int* in_sizes, int n_in,
                              void* d_out, int out_size)
{
    const float* ctx = (const float*)d_in[0];
    const float* qst = (const float*)d_in[1];
    const int*   cl  = (const int*)d_in[2];
    const int*   ql  = (const int*)d_in[3];
    const float* aw  = (const float*)d_in[4];
    float* G = (float*)d_out;

    cudaFuncSetAttribute(bidaf_k1_mma, cudaFuncAttributeMaxDynamicSharedMemorySize, SMEM_DYN);

    dim3 g1(TDIM / 128, BDIM);
    bidaf_k1_mma<<<g1, 256, SMEM_DYN>>>(ctx, qst, cl, ql, aw, G);
    bidaf_k2a<<<BDIM, 256>>>();
    bidaf_k2b<<<dim3(8, BDIM), 256>>>(ctx);
    bidaf_k3<<<(BDIM * TDIM * DDIM / 4) / 256, 256>>>(ctx, cl, G);
}